// round 12
// baseline (speedup 1.0000x reference)
#include <cuda_runtime.h>
#include <stdint.h>

#define NB 64
#define NS 512
#define ND 768
#define NROWS (NB * NS)          // 32768
#define ROWS_PER_BLOCK 8         // one row per warp
#define THREADS 256
#define F8_PER_LANE 3            // 768 floats / (32 lanes * 8 floats)

__device__ __forceinline__ uint32_t rotl32(uint32_t x, int r) {
    return (x << r) | (x >> (32 - r));
}

// JAX threefry2x32-20, key = (0, 42), partitionable path:
//   counter for element i is (hi, lo) = (0, i); 32-bit output = lane0 ^ lane1
__device__ __forceinline__ uint32_t jax_threefry_bits_partitionable(uint32_t i) {
    const uint32_t ks0 = 0u;
    const uint32_t ks1 = 42u;
    const uint32_t ks2 = 0u ^ 42u ^ 0x1BD11BDAu;

    uint32_t x0 = 0u + ks0;   // counts_hi = 0
    uint32_t x1 = i + ks1;    // counts_lo = i

#define TF_R4(r0, r1, r2, r3)                                   \
    x0 += x1; x1 = rotl32(x1, r0); x1 ^= x0;                    \
    x0 += x1; x1 = rotl32(x1, r1); x1 ^= x0;                    \
    x0 += x1; x1 = rotl32(x1, r2); x1 ^= x0;                    \
    x0 += x1; x1 = rotl32(x1, r3); x1 ^= x0;

    TF_R4(13, 15, 26, 6);  x0 += ks1; x1 += ks2 + 1u;
    TF_R4(17, 29, 16, 24); x0 += ks2; x1 += ks0 + 2u;
    TF_R4(13, 15, 26, 6);  x0 += ks0; x1 += ks1 + 3u;
    TF_R4(17, 29, 16, 24); x0 += ks1; x1 += ks2 + 4u;
    TF_R4(13, 15, 26, 6);  x0 += ks2; x1 += ks0 + 5u;
#undef TF_R4

    return x0 ^ x1;
}

struct f8 { float v[8]; };

// 256-bit global load/store (Blackwell LDG.E.256 / STG.E.256).
__device__ __forceinline__ f8 ldg256(const float* p) {
    f8 r;
    asm volatile("ld.global.v8.f32 {%0,%1,%2,%3,%4,%5,%6,%7}, [%8];"
                 : "=f"(r.v[0]), "=f"(r.v[1]), "=f"(r.v[2]), "=f"(r.v[3]),
                   "=f"(r.v[4]), "=f"(r.v[5]), "=f"(r.v[6]), "=f"(r.v[7])
                 : "l"(p));
    return r;
}
__device__ __forceinline__ void stg256(float* p, const f8& r) {
    asm volatile("st.global.v8.f32 [%0], {%1,%2,%3,%4,%5,%6,%7,%8};"
                 :: "l"(p),
                    "f"(r.v[0]), "f"(r.v[1]), "f"(r.v[2]), "f"(r.v[3]),
                    "f"(r.v[4]), "f"(r.v[5]), "f"(r.v[6]), "f"(r.v[7])
                 : "memory");
}

__global__ __launch_bounds__(THREADS)
void position_dropout_kernel(const float* __restrict__ x,
                             const int* __restrict__ abi,   // [B,2]
                             const int* __restrict__ tlen,  // [B]
                             const int* __restrict__ alen,  // [B]
                             float* __restrict__ out) {
    const int t = threadIdx.x;
    const int lane = t & 31;
    const int row = blockIdx.x * ROWS_PER_BLOCK + (t >> 5);   // one row per warp
    const uint32_t base = (uint32_t)row * ND + (uint32_t)lane * 8u; // float index

    // Front-batch 3 independent 256-bit loads (same bytes as 6x float4, half
    // the LDG count). The RNG chain below (lane 0 only) overlaps with them.
    f8 v[F8_PER_LANE];
#pragma unroll
    for (int k = 0; k < F8_PER_LANE; k++)
        v[k] = ldg256(x + base + 256u * k);

    float sc = 0.0f;
    if (lane == 0) {
        const int b = row >> 9;                 // row / NS
        const int j = row & (NS - 1);           // row % NS

        const int2 bb = *(const int2*)(abi + 2 * b);
        const int tli = tlen[b];
        const float jf  = (float)j;
        const float b0f = (float)bb.x;
        const float b1f = (float)bb.y;
        const float tlf = (float)tli;
        const float ctx = (float)(tli - alen[b]);

        // Exact IEEE divisions so fast-math can't shift the comparison boundary.
        float prox;
        if (jf < b0f)       prox = 1.0f - __fdiv_rn(b0f - jf, ctx);
        else if (jf <= b1f) prox = __fdiv_rn(1.0f, ctx);
        else                prox = 1.0f - __fdiv_rn(jf - b1f, ctx);
        if (!(jf < tlf)) prox = 0.0f;
        prox = fminf(fmaxf(prox, 0.0f), 1.0f);

        const uint32_t bits = jax_threefry_bits_partitionable((uint32_t)row);
        const float u = __uint_as_float((bits >> 9) | 0x3f800000u) - 1.0f;
        const float mask = (u < prox) ? 1.0f : 0.0f;

        sc = __fdiv_rn(mask, prox + 1e-5f);
    }
    sc = __shfl_sync(0xffffffffu, sc, 0);

#pragma unroll
    for (int k = 0; k < F8_PER_LANE; k++) {
        f8 w = v[k];
#pragma unroll
        for (int e = 0; e < 8; e++) w.v[e] *= sc;
        stg256(out + base + 256u * k, w);
    }
}

extern "C" void kernel_launch(void* const* d_in, const int* in_sizes, int n_in,
                              void* d_out, int out_size) {
    const float* x  = (const float*)d_in[0];
    const int* abi  = (const int*)d_in[1];
    const int* tlen = (const int*)d_in[2];
    const int* alen = (const int*)d_in[3];
    float* out = (float*)d_out;

    const int nblocks = NROWS / ROWS_PER_BLOCK;          // 4096
    position_dropout_kernel<<<nblocks, THREADS>>>(x, abi, tlen, alen, out);
}

// round 13
// speedup vs baseline: 1.3101x; 1.3101x over previous
#include <cuda_runtime.h>
#include <stdint.h>

#define NB 64
#define NS 512
#define ND 768
#define NROWS (NB * NS)          // 32768
#define F4_PER_ROW (ND / 4)      // 192
#define ROWS_PER_BLOCK 8         // one row per warp
#define THREADS 256
#define F4_PER_LANE 6            // 192 / 32

__device__ __forceinline__ uint32_t rotl32(uint32_t x, int r) {
    return (x << r) | (x >> (32 - r));
}

// JAX threefry2x32-20, key = (0, 42), partitionable path:
//   counter for element i is (hi, lo) = (0, i); 32-bit output = lane0 ^ lane1
__device__ __forceinline__ uint32_t jax_threefry_bits_partitionable(uint32_t i) {
    const uint32_t ks0 = 0u;
    const uint32_t ks1 = 42u;
    const uint32_t ks2 = 0u ^ 42u ^ 0x1BD11BDAu;

    uint32_t x0 = 0u + ks0;   // counts_hi = 0
    uint32_t x1 = i + ks1;    // counts_lo = i

#define TF_R4(r0, r1, r2, r3)                                   \
    x0 += x1; x1 = rotl32(x1, r0); x1 ^= x0;                    \
    x0 += x1; x1 = rotl32(x1, r1); x1 ^= x0;                    \
    x0 += x1; x1 = rotl32(x1, r2); x1 ^= x0;                    \
    x0 += x1; x1 = rotl32(x1, r3); x1 ^= x0;

    TF_R4(13, 15, 26, 6);  x0 += ks1; x1 += ks2 + 1u;
    TF_R4(17, 29, 16, 24); x0 += ks2; x1 += ks0 + 2u;
    TF_R4(13, 15, 26, 6);  x0 += ks0; x1 += ks1 + 3u;
    TF_R4(17, 29, 16, 24); x0 += ks1; x1 += ks2 + 4u;
    TF_R4(13, 15, 26, 6);  x0 += ks2; x1 += ks0 + 5u;
#undef TF_R4

    return x0 ^ x1;
}

__global__ __launch_bounds__(THREADS)
void position_dropout_kernel(const float4* __restrict__ x,
                             const int* __restrict__ abi,   // [B,2]
                             const int* __restrict__ tlen,  // [B]
                             const int* __restrict__ alen,  // [B]
                             float4* __restrict__ out) {
    const int t = threadIdx.x;
    const int lane = t & 31;
    const int row = blockIdx.x * ROWS_PER_BLOCK + (t >> 5);   // one row per warp
    const uint32_t base = (uint32_t)row * F4_PER_ROW + lane;

    // Scale FIRST: ~60% of rows have mask=0 -> sc=0 -> out row is zeros
    // regardless of x, so we can skip reading 3KB of x per such row.
    float sc = 0.0f;
    if (lane == 0) {
        const int b = row >> 9;                 // row / NS
        const int j = row & (NS - 1);           // row % NS

        const int2 bb = *(const int2*)(abi + 2 * b);
        const int tli = tlen[b];
        const float jf  = (float)j;
        const float b0f = (float)bb.x;
        const float b1f = (float)bb.y;
        const float tlf = (float)tli;
        const float ctx = (float)(tli - alen[b]);

        // Exact IEEE divisions so fast-math can't shift the comparison boundary.
        float prox;
        if (jf < b0f)       prox = 1.0f - __fdiv_rn(b0f - jf, ctx);
        else if (jf <= b1f) prox = __fdiv_rn(1.0f, ctx);
        else                prox = 1.0f - __fdiv_rn(jf - b1f, ctx);
        if (!(jf < tlf)) prox = 0.0f;
        prox = fminf(fmaxf(prox, 0.0f), 1.0f);

        const uint32_t bits = jax_threefry_bits_partitionable((uint32_t)row);
        const float u = __uint_as_float((bits >> 9) | 0x3f800000u) - 1.0f;
        const float mask = (u < prox) ? 1.0f : 0.0f;

        sc = __fdiv_rn(mask, prox + 1e-5f);     // exactly 0.0f when mask==0
    }
    sc = __shfl_sync(0xffffffffu, sc, 0);

    // Warp-uniform branch (one row per warp -> no divergence).
    if (sc != 0.0f) {
        float4 v[F4_PER_LANE];
#pragma unroll
        for (int k = 0; k < F4_PER_LANE; k++)
            v[k] = x[base + 32u * k];
#pragma unroll
        for (int k = 0; k < F4_PER_LANE; k++) {
            float4 w = v[k];
            w.x *= sc; w.y *= sc; w.z *= sc; w.w *= sc;
            out[base + 32u * k] = w;
        }
    } else {
        const float4 z = make_float4(0.0f, 0.0f, 0.0f, 0.0f);
#pragma unroll
        for (int k = 0; k < F4_PER_LANE; k++)
            out[base + 32u * k] = z;
    }
}

extern "C" void kernel_launch(void* const* d_in, const int* in_sizes, int n_in,
                              void* d_out, int out_size) {
    const float4* x = (const float4*)d_in[0];
    const int* abi  = (const int*)d_in[1];
    const int* tlen = (const int*)d_in[2];
    const int* alen = (const int*)d_in[3];
    float4* out = (float4*)d_out;

    const int nblocks = NROWS / ROWS_PER_BLOCK;          // 4096
    position_dropout_kernel<<<nblocks, THREADS>>>(x, abi, tlen, alen, out);
}